// round 1
// baseline (speedup 1.0000x reference)
#include <cuda_runtime.h>
#include <cstdint>

#define SEQ 4096
#define HID 256
#define EMB 256

// ---------------------------------------------------------------------------
// Scratch: x_proj[t][j] (4096 x 256 fp32 = 4 MB). Device global (no alloc).
// ---------------------------------------------------------------------------
__device__ float g_xproj[SEQ * HID];

// ---------------------------------------------------------------------------
// Phase 1: x_proj = embedding[tokens] @ wx_w.T + wx_b
// 256 blocks x 256 threads; block handles 16 tokens; thread j owns wx_w row j.
// ---------------------------------------------------------------------------
#define TOK_PER_BLK 16

__global__ __launch_bounds__(256) void xproj_kernel(
    const int* __restrict__ tokens,
    const float* __restrict__ embedding,
    const float* __restrict__ wx_w,
    const float* __restrict__ wx_b)
{
    __shared__ float emb_sm[TOK_PER_BLK * EMB];
    const int tid = threadIdx.x;
    const int t0  = blockIdx.x * TOK_PER_BLK;

    // Gather 16 embedding rows into smem (each iteration: 256 threads = 1 row)
    #pragma unroll
    for (int i = 0; i < TOK_PER_BLK; i++) {
        long tok = (long)tokens[t0 + i];
        emb_sm[i * EMB + tid] = embedding[tok * (long)EMB + tid];
    }
    __syncthreads();

    float acc[TOK_PER_BLK];
    #pragma unroll
    for (int i = 0; i < TOK_PER_BLK; i++) acc[i] = 0.f;

    const float4* wrow = reinterpret_cast<const float4*>(wx_w + tid * EMB);
    #pragma unroll 4
    for (int k4 = 0; k4 < EMB / 4; k4++) {
        float4 w = wrow[k4];
        #pragma unroll
        for (int i = 0; i < TOK_PER_BLK; i++) {
            float4 e = *reinterpret_cast<const float4*>(&emb_sm[i * EMB + 4 * k4]);
            acc[i] += w.x * e.x + w.y * e.y + w.z * e.z + w.w * e.w;
        }
    }

    const float b = wx_b[tid];
    #pragma unroll
    for (int i = 0; i < TOK_PER_BLK; i++)
        g_xproj[(t0 + i) * HID + tid] = acc[i] + b;
}

// ---------------------------------------------------------------------------
// Phase 2: serial recurrence, 2-CTA cluster.
//   CTA rank r owns output rows [r*128, r*128+128). 512 threads/CTA.
//   Thread t: output o = t & 127, k-segment seg = t >> 7 (64 k each).
//   All 32768 per-CTA weights live in registers (64 floats/thread).
//   h replicated per CTA in smem (double-buffered); halves exchanged via
//   st.shared::cluster; one barrier.cluster (release/acquire) per step.
// ---------------------------------------------------------------------------
#define NCTA 2
#define THREADS2 512
#define OUT_PER_CTA (HID / NCTA)        // 128
#define SEGS (THREADS2 / OUT_PER_CTA)   // 4
#define KSEG (HID / SEGS)               // 64

__device__ __forceinline__ uint32_t smem_u32(const void* p) {
    uint32_t a;
    asm("{ .reg .u64 t; cvta.to.shared.u64 t, %1; cvt.u32.u64 %0, t; }"
        : "=r"(a) : "l"(p));
    return a;
}
__device__ __forceinline__ uint32_t mapa_peer(uint32_t a, uint32_t rank) {
    uint32_t r;
    asm("mapa.shared::cluster.u32 %0, %1, %2;" : "=r"(r) : "r"(a), "r"(rank));
    return r;
}
__device__ __forceinline__ void st_remote_f32(uint32_t a, float v) {
    asm volatile("st.shared::cluster.f32 [%0], %1;" :: "r"(a), "f"(v) : "memory");
}

__global__ __launch_bounds__(THREADS2, 1) __cluster_dims__(NCTA, 1, 1)
void rnn_kernel(const float* __restrict__ wh_w,
                const float* __restrict__ wh_b,
                float* __restrict__ out)
{
    __shared__ float hbuf[2][HID];
    __shared__ float psum[OUT_PER_CTA * SEGS];

    const int tid = threadIdx.x;
    uint32_t rank;
    asm("mov.u32 %0, %%cluster_ctarank;" : "=r"(rank));

    const int olocal = tid & (OUT_PER_CTA - 1);
    const int seg    = tid >> 7;
    const int oglob  = (int)rank * OUT_PER_CTA + olocal;

    // Register-resident weight slice: wh_w[oglob][seg*64 .. seg*64+64)
    float w[KSEG];
    #pragma unroll
    for (int i = 0; i < KSEG; i++)
        w[i] = wh_w[oglob * HID + seg * KSEG + i];

    // h0 = 0
    for (int i = tid; i < HID; i += THREADS2) hbuf[0][i] = 0.f;

    const bool writer = (tid < OUT_PER_CTA);   // seg==0 threads finalize outputs
    float bias = 0.f, xp_cur = 0.f;
    if (writer) {
        bias   = wh_b[oglob];
        xp_cur = g_xproj[oglob];               // t = 0
    }
    __syncthreads();
    asm volatile("barrier.cluster.arrive.aligned;" ::: "memory");
    asm volatile("barrier.cluster.wait.aligned;"   ::: "memory");

    const uint32_t peer    = rank ^ 1u;
    const uint32_t h0_loc  = smem_u32(&hbuf[0][0]);
    const uint32_t h0_peer = mapa_peer(h0_loc, peer);

    int cur = 0;
    for (int t = 0; t < SEQ; t++) {
        // Prefetch next step's x_proj early (L2-resident, latency hidden)
        float xp_next = 0.f;
        if (writer && (t + 1 < SEQ))
            xp_next = __ldg(&g_xproj[(t + 1) * HID + oglob]);

        // Partial dot: 64 register-weight FMAs, h via LDS.128 broadcast
        const float* h = &hbuf[cur][seg * KSEG];
        float a0 = 0.f, a1 = 0.f, a2 = 0.f, a3 = 0.f;
        #pragma unroll
        for (int i = 0; i < KSEG; i += 4) {
            float4 hv = *reinterpret_cast<const float4*>(&h[i]);
            a0 += w[i + 0] * hv.x;
            a1 += w[i + 1] * hv.y;
            a2 += w[i + 2] * hv.z;
            a3 += w[i + 3] * hv.w;
        }
        psum[olocal * SEGS + seg] = (a0 + a1) + (a2 + a3);
        __syncthreads();

        const int nxt = cur ^ 1;
        if (writer) {
            float4 p = *reinterpret_cast<const float4*>(&psum[olocal * SEGS]);
            float s  = ((p.x + p.y) + (p.z + p.w)) + bias + xp_cur;
            float hn = 1.f / (1.f + __expf(-s));
            hbuf[nxt][oglob] = hn;                                    // local copy
            st_remote_f32(h0_peer + (uint32_t)(nxt * HID + oglob) * 4u, hn); // peer copy
            xp_cur = xp_next;
        }
        // release our writes / acquire peer's
        asm volatile("barrier.cluster.arrive.aligned;" ::: "memory");
        asm volatile("barrier.cluster.wait.aligned;"   ::: "memory");
        cur = nxt;
    }

    if (writer) out[oglob] = hbuf[cur][oglob];
}

// ---------------------------------------------------------------------------
// kernel_launch
//   d_in: [0] tokens i32[4096], [1] embedding f32[128000*256],
//         [2] wx_w f32[256*256], [3] wx_b f32[256],
//         [4] wh_w f32[256*256], [5] wh_b f32[256]
//   d_out: f32[256]
// ---------------------------------------------------------------------------
extern "C" void kernel_launch(void* const* d_in, const int* in_sizes, int n_in,
                              void* d_out, int out_size)
{
    const int*   tokens    = (const int*)d_in[0];
    const float* embedding = (const float*)d_in[1];
    const float* wx_w      = (const float*)d_in[2];
    const float* wx_b      = (const float*)d_in[3];
    const float* wh_w      = (const float*)d_in[4];
    const float* wh_b      = (const float*)d_in[5];
    float*       out       = (float*)d_out;

    xproj_kernel<<<SEQ / TOK_PER_BLK, 256>>>(tokens, embedding, wx_w, wx_b);
    rnn_kernel<<<NCTA, THREADS2>>>(wh_w, wh_b, out);
}